// round 4
// baseline (speedup 1.0000x reference)
#include <cuda_runtime.h>
#include <cuda_fp8.h>
#include <cstdint>

#define TOKENS 4096
#define HID    4096
#define VOCAB  32000
#define NCHUNK 16
#define MT     32      // 4096/128 m tiles
#define NTL    125     // 32000/256 n tiles
#define KT128  32      // 4096/128 k stage-chunks

// ---------------- device scratch (static; no cudaMalloc) -------------------
// fp8 fragment-ordered operands for mma.sync m16n8k32 e4m3:
// g_xa: A block (kt,mt) = 16384 B at ((kt*MT+mt)<<14)
//       off = ((ka*8 + ma)*32 + lane)*16 + reg*4 + byte
// g_wb: B block (kt,nt) = 32768 B at ((kt*NTL+nt)<<15)
//       off = ((ka*32 + na)*32 + lane)*8 + reg*4 + byte
__device__ __align__(16) unsigned char g_xa[(size_t)TOKENS * HID];
__device__ __align__(16) unsigned char g_wb[(size_t)VOCAB * HID];
__device__ float g_ws[VOCAB];
__device__ float g_cmax[NCHUNK * HID];
__device__ int   g_tmax_i[NCHUNK];
__device__ float g_sx[NCHUNK * HID];
__device__ float g_mult[NCHUNK * HID];

// ------------------------------ helpers ------------------------------------
__device__ __forceinline__ float qclamp(float x, float s) {
    // matches jnp.clip(jnp.round(x/s), -8, 7), round-half-to-even, rn divide
    return fminf(fmaxf(rintf(__fdiv_rn(x, s)), -8.0f), 7.0f);
}
__device__ __forceinline__ unsigned char fp8_of(float v) {
    return (unsigned char)__nv_cvt_float_to_fp8(v, __NV_SATFINITE, __NV_E4M3);
}
__device__ __forceinline__ uint32_t pack4(unsigned char a, unsigned char b,
                                          unsigned char c, unsigned char d) {
    return (uint32_t)a | ((uint32_t)b << 8) | ((uint32_t)c << 16) | ((uint32_t)d << 24);
}
__device__ __forceinline__ void mma_fp8(float* c, const uint32_t* a,
                                        const uint32_t* b) {
    asm volatile(
        "mma.sync.aligned.m16n8k32.row.col.f32.e4m3.e4m3.f32 "
        "{%0,%1,%2,%3}, {%4,%5,%6,%7}, {%8,%9}, {%0,%1,%2,%3};"
        : "+f"(c[0]), "+f"(c[1]), "+f"(c[2]), "+f"(c[3])
        : "r"(a[0]), "r"(a[1]), "r"(a[2]), "r"(a[3]), "r"(b[0]), "r"(b[1]));
}
#define CP_ASYNC16(dst_u32, src_ptr) \
    asm volatile("cp.async.cg.shared.global [%0], [%1], 16;" \
                 :: "r"(dst_u32), "l"(src_ptr) : "memory")
#define CP_COMMIT()  asm volatile("cp.async.commit_group;" ::: "memory")
#define CP_WAIT2()   asm volatile("cp.async.wait_group 2;" ::: "memory")

__device__ __forceinline__ uint32_t smem_u32(const void* p) {
    uint32_t a;
    asm("{ .reg .u64 t; cvta.to.shared.u64 t, %1; cvt.u32.u64 %0, t; }"
        : "=r"(a) : "l"(p));
    return a;
}

// ------------------------------- prep kernels ------------------------------
__global__ void zero_tmax_kernel() {
    if (threadIdx.x < NCHUNK) g_tmax_i[threadIdx.x] = 0;
}

// per-row weight scale: warp per vocab row
__global__ void w_scale_kernel(const float* __restrict__ W) {
    const int w = threadIdx.x >> 5, lane = threadIdx.x & 31;
    const int v = blockIdx.x * 8 + w;
    const float4* row = reinterpret_cast<const float4*>(W + (size_t)v * HID);
    float m = 0.0f;
#pragma unroll
    for (int j = 0; j < 32; j++) {
        float4 f = row[lane + j * 32];
        m = fmaxf(m, fmaxf(fmaxf(fabsf(f.x), fabsf(f.y)),
                           fmaxf(fabsf(f.z), fabsf(f.w))));
    }
#pragma unroll
    for (int s = 16; s > 0; s >>= 1)
        m = fmaxf(m, __shfl_xor_sync(0xFFFFFFFFu, m, s));
    if (lane == 0) g_ws[v] = fmaxf(__fdiv_rn(m, 7.0f), 1e-9f);
}

// pack weight block (nt, kt): 256 rows x 128 K -> fragment-ordered 32 KB fp8
__global__ void w_pack_kernel(const float* __restrict__ W) {
    const int nt = blockIdx.x, kt = blockIdx.y;
    const int t = threadIdx.x;
    __shared__ __align__(16) unsigned char stg[32768];
    const int v = nt * 256 + t, na = t >> 3, nl = t & 7;
    const float* wrow = W + (size_t)v * HID + kt * 128;
    const float s = g_ws[v];
#pragma unroll
    for (int i = 0; i < 32; i++) {
        const int k0 = 4 * i;                 // 4 consecutive fp8 = 1 reg
        const int ka = k0 >> 5;
        const int half = (k0 >> 4) & 1;       // b0 vs b1
        const int kq = (k0 >> 2) & 3;
        const int lane = nl * 4 + kq;
        const uint32_t off = (uint32_t)(((ka * 32 + na) * 32 + lane) * 8 + half * 4);
        *reinterpret_cast<uint32_t*>(stg + off) =
            pack4(fp8_of(qclamp(wrow[k0],     s)),
                  fp8_of(qclamp(wrow[k0 + 1], s)),
                  fp8_of(qclamp(wrow[k0 + 2], s)),
                  fp8_of(qclamp(wrow[k0 + 3], s)));
    }
    __syncthreads();
    uint4* dst = reinterpret_cast<uint4*>(g_wb + ((size_t)(kt * NTL + nt) << 15));
    const uint4* src = reinterpret_cast<const uint4*>(stg);
#pragma unroll
    for (int i = 0; i < 8; i++) dst[t + i * 256] = src[t + i * 256];
}

// per-(chunk, channel) abs max over 256 rows + per-chunk max
__global__ void chunk_cmax_kernel(const float* __restrict__ X) {
    const int c  = blockIdx.x;
    const int ch = blockIdx.y * 256 + threadIdx.x;
    const float* p = X + (size_t)c * 256 * HID + ch;
    float m = 0.0f;
#pragma unroll 8
    for (int r = 0; r < 256; r++) m = fmaxf(m, fabsf(p[(size_t)r * HID]));
    g_cmax[c * HID + ch] = m;
    __shared__ float red[256];
    red[threadIdx.x] = m;
    __syncthreads();
    for (int s = 128; s > 0; s >>= 1) {
        if (threadIdx.x < s)
            red[threadIdx.x] = fmaxf(red[threadIdx.x], red[threadIdx.x + s]);
        __syncthreads();
    }
    if (threadIdx.x == 0)
        atomicMax(&g_tmax_i[c], __float_as_int(red[0]));  // nonneg floats
}

__global__ void chunk_scales_kernel() {
    const int idx = blockIdx.x * 256 + threadIdx.x;   // NCHUNK*HID = 65536
    const int c = idx >> 12;
    const float tmax = __int_as_float(g_tmax_i[c]);
    const float cm = g_cmax[idx];
    int b = 0;
#pragma unroll
    for (int i = 0; i < 13; i++) b += (cm > ldexpf(tmax, i - 13)) ? 1 : 0;
    g_sx[idx]   = fmaxf(__fdiv_rn(ldexpf(tmax, b - 13), 7.0f), 1e-9f);
    g_mult[idx] = ldexpf(1.0f, b - 8);   // exact pow2, exact in e4m3
}

// pack activation block (mt, kt): 128 rows x 128 K -> fragment-ordered 16 KB
__global__ void x_pack_kernel(const float* __restrict__ X) {
    const int mt = blockIdx.x, kt = blockIdx.y;
    const int m = threadIdx.x;                 // 128 threads, one token row each
    __shared__ __align__(16) unsigned char stg[16384];
    const int token = mt * 128 + m;
    const int chunk = token >> 8;
    const float* xrow = X + (size_t)token * HID + kt * 128;
    const float* sx = g_sx   + chunk * HID + kt * 128;
    const float* ml = g_mult + chunk * HID + kt * 128;
    const int ma = m >> 4, mi = m & 15;
    const int hi = mi >> 3, rl = mi & 7;
#pragma unroll
    for (int i = 0; i < 32; i++) {
        const int k0 = 4 * i;
        const int ka = k0 >> 5;
        const int khalf = (k0 >> 4) & 1;
        const int kq = (k0 >> 2) & 3;
        const int reg = khalf * 2 + hi;        // a0..a3
        const int lane = rl * 4 + kq;
        const uint32_t off = (uint32_t)(((ka * 8 + ma) * 32 + lane) * 16 + reg * 4);
        *reinterpret_cast<uint32_t*>(stg + off) =
            pack4(fp8_of(qclamp(xrow[k0],     sx[k0])     * ml[k0]),
                  fp8_of(qclamp(xrow[k0 + 1], sx[k0 + 1]) * ml[k0 + 1]),
                  fp8_of(qclamp(xrow[k0 + 2], sx[k0 + 2]) * ml[k0 + 2]),
                  fp8_of(qclamp(xrow[k0 + 3], sx[k0 + 3]) * ml[k0 + 3]));
    }
    __syncthreads();
    uint4* dst = reinterpret_cast<uint4*>(g_xa + ((size_t)(kt * MT + mt) << 14));
    const uint4* src = reinterpret_cast<const uint4*>(stg);
#pragma unroll
    for (int i = 0; i < 8; i++) dst[m + i * 128] = src[m + i * 128];
}

// --------------------------------- GEMM ------------------------------------
// 128(M) x 256(N) CTA tile, 8 warps (2m x 4n) of 64x64, K stage 128, 4 stages.
#define STAGES 4
#define STG_BYTES 49152   // A 16 KB + B 32 KB (fp8)

__global__ void __launch_bounds__(256, 1) gemm_kernel(float* __restrict__ out) {
    extern __shared__ __align__(16) unsigned char dyn[];
    __shared__ float s_sw[256];
    const int tid = threadIdx.x;
    const int wid = tid >> 5, lid = tid & 31;
    const int mt = blockIdx.x, nt = blockIdx.y;
    const int wm = wid >> 2, wn = wid & 3;
    const uint32_t sbase = smem_u32(dyn);

    s_sw[tid] = g_ws[nt * 256 + tid];

    auto fetch = [&](int s, int kt) {
        const uint32_t d = sbase + s * STG_BYTES + tid * 16;
        const unsigned char* a = g_xa + (((size_t)kt * MT + mt) << 14) + tid * 16;
        const unsigned char* b = g_wb + (((size_t)kt * NTL + nt) << 15) + tid * 16;
#pragma unroll
        for (int i = 0; i < 4; i++) CP_ASYNC16(d + i * 4096, a + i * 4096);
#pragma unroll
        for (int i = 0; i < 8; i++)
            CP_ASYNC16(d + 16384 + i * 4096, b + i * 4096);
    };

    float acc[4][8][4];
#pragma unroll
    for (int i = 0; i < 4; i++)
#pragma unroll
        for (int j = 0; j < 8; j++)
#pragma unroll
            for (int k = 0; k < 4; k++) acc[i][j][k] = 0.0f;

    fetch(0, 0); CP_COMMIT();
    fetch(1, 1); CP_COMMIT();
    fetch(2, 2); CP_COMMIT();

#pragma unroll 1
    for (int kt = 0; kt < KT128; kt++) {
        CP_WAIT2();
        __syncthreads();
        if (kt + 3 < KT128) fetch((kt + 3) & 3, kt + 3);
        CP_COMMIT();
        const unsigned char* st = dyn + (kt & 3) * STG_BYTES;
#pragma unroll
        for (int ka = 0; ka < 4; ka++) {
            uint32_t af[4][4], bf[8][2];
#pragma unroll
            for (int ma = 0; ma < 4; ma++) {
                const uint4 q = *reinterpret_cast<const uint4*>(
                    st + (ka * 8 + wm * 4 + ma) * 512 + lid * 16);
                af[ma][0] = q.x; af[ma][1] = q.y; af[ma][2] = q.z; af[ma][3] = q.w;
            }
#pragma unroll
            for (int na = 0; na < 8; na++) {
                const uint2 q = *reinterpret_cast<const uint2*>(
                    st + 16384 + (ka * 32 + wn * 8 + na) * 256 + lid * 8);
                bf[na][0] = q.x; bf[na][1] = q.y;
            }
#pragma unroll
            for (int ma = 0; ma < 4; ma++)
#pragma unroll
                for (int na = 0; na < 8; na++)
                    mma_fp8(acc[ma][na], af[ma], bf[na]);
        }
    }

    // epilogue: acc * alpha[chunk] * sw[v]
    const float alpha =
        __fdiv_rn(__int_as_float(g_tmax_i[mt >> 1]), 7.0f) * 0.03125f;
    const int row_base = mt * 128 + wm * 64;
    const int col_cta = nt * 256;
#pragma unroll
    for (int ma = 0; ma < 4; ma++) {
#pragma unroll
        for (int na = 0; na < 8; na++) {
            const int r0 = row_base + ma * 16 + (lid >> 2);
            const int c0 = wn * 64 + na * 8 + (lid & 3) * 2;
            const float f0 = s_sw[c0] * alpha, f1 = s_sw[c0 + 1] * alpha;
            float* p = out + (size_t)r0 * VOCAB + col_cta + c0;
            float2 v0, v1;
            v0.x = acc[ma][na][0] * f0; v0.y = acc[ma][na][1] * f1;
            v1.x = acc[ma][na][2] * f0; v1.y = acc[ma][na][3] * f1;
            *reinterpret_cast<float2*>(p) = v0;
            *reinterpret_cast<float2*>(p + (size_t)8 * VOCAB) = v1;
        }
    }
}

// ------------------------------- launcher ----------------------------------
extern "C" void kernel_launch(void* const* d_in, const int* in_sizes, int n_in,
                              void* d_out, int out_size) {
    const float* hs = (const float*)d_in[0];   // [2,2048,4096]
    const float* W  = (const float*)d_in[1];   // [32000,4096]
    float* out = (float*)d_out;

    cudaFuncSetAttribute(gemm_kernel,
                         cudaFuncAttributeMaxDynamicSharedMemorySize,
                         STAGES * STG_BYTES);

    zero_tmax_kernel<<<1, 32>>>();
    w_scale_kernel<<<VOCAB / 8, 256>>>(W);
    w_pack_kernel<<<dim3(NTL, KT128), 256>>>(W);
    chunk_cmax_kernel<<<dim3(NCHUNK, HID / 256), 256>>>(hs);
    chunk_scales_kernel<<<NCHUNK * HID / 256, 256>>>();
    x_pack_kernel<<<dim3(MT, KT128), 128>>>(hs);
    gemm_kernel<<<dim3(MT, NTL), 256, STAGES * STG_BYTES>>>(out);
}

// round 5
// speedup vs baseline: 1.2859x; 1.2859x over previous
#include <cuda_runtime.h>
#include <cstdint>

#define TOKENS 4096
#define HID    4096
#define VOCAB  32000
#define NCHUNK 16
#define MT     32      // 4096/128 m tiles
#define NTL    125     // 32000/256 n tiles
#define KT64   64      // 4096/64 k stage-chunks

// ---------------- device scratch (static; no cudaMalloc) -------------------
// bf16 fragment-ordered operands for mma.sync m16n8k16:
// g_xa: A block (kt,mt) = 16384 B at ((kt*MT+mt)<<14)
//       off = (ka*8 + ma)*512 + ((mm&7)*4 + ((kk&7)>>1))*16 + ((kk>>3)*2 + (mm>>3))*4
// g_wb: B block (kt,nt) = 32768 B at ((kt*NTL+nt)<<15), K-PAIRED:
//       off = ((kp*32 + na)*32 + lane)*16 + (ka&1)*8 + reg*4   (kp = ka>>1)
__device__ __align__(16) unsigned char g_xa[(size_t)TOKENS * HID * 2];
__device__ __align__(16) unsigned char g_wb[(size_t)VOCAB * HID * 2];
__device__ float g_ws[VOCAB];
__device__ float g_cmax[NCHUNK * HID];
__device__ int   g_tmax_i[NCHUNK];
__device__ float g_sx[NCHUNK * HID];
__device__ float g_mult[NCHUNK * HID];

// ------------------------------ helpers ------------------------------------
__device__ __forceinline__ uint32_t smem_u32(const void* p) {
    uint32_t a;
    asm("{ .reg .u64 t; cvta.to.shared.u64 t, %1; cvt.u32.u64 %0, t; }"
        : "=r"(a) : "l"(p));
    return a;
}
__device__ __forceinline__ float qclamp(float x, float s) {
    // matches jnp.clip(jnp.round(x/s), -8, 7), round-half-to-even, rn divide
    return fminf(fmaxf(rintf(__fdiv_rn(x, s)), -8.0f), 7.0f);
}
__device__ __forceinline__ uint32_t bf16x2(float lo, float hi) {
    uint32_t r;
    asm("cvt.rn.bf16x2.f32 %0, %1, %2;" : "=r"(r) : "f"(hi), "f"(lo));
    return r;
}
__device__ __forceinline__ void mma16816(float* c, const uint32_t* a,
                                         const uint32_t* b) {
    asm volatile(
        "mma.sync.aligned.m16n8k16.row.col.f32.bf16.bf16.f32 "
        "{%0,%1,%2,%3}, {%4,%5,%6,%7}, {%8,%9}, {%0,%1,%2,%3};"
        : "+f"(c[0]), "+f"(c[1]), "+f"(c[2]), "+f"(c[3])
        : "r"(a[0]), "r"(a[1]), "r"(a[2]), "r"(a[3]), "r"(b[0]), "r"(b[1]));
}
#define CP_ASYNC16(dst_u32, src_ptr) \
    asm volatile("cp.async.cg.shared.global [%0], [%1], 16;" \
                 :: "r"(dst_u32), "l"(src_ptr) : "memory")
#define CP_COMMIT()  asm volatile("cp.async.commit_group;" ::: "memory")
#define CP_WAIT2()   asm volatile("cp.async.wait_group 2;" ::: "memory")

// ------------------------------- prep kernels ------------------------------
// per-row weight scale (warp per vocab row); block 0 also zeroes g_tmax_i
__global__ void w_scale_kernel(const float* __restrict__ W) {
    if (blockIdx.x == 0 && threadIdx.x < NCHUNK) g_tmax_i[threadIdx.x] = 0;
    const int w = threadIdx.x >> 5, lane = threadIdx.x & 31;
    const int v = blockIdx.x * 8 + w;
    const float4* row = reinterpret_cast<const float4*>(W + (size_t)v * HID);
    float m = 0.0f;
#pragma unroll
    for (int j = 0; j < 32; j++) {
        float4 f = row[lane + j * 32];
        m = fmaxf(m, fmaxf(fmaxf(fabsf(f.x), fabsf(f.y)),
                           fmaxf(fabsf(f.z), fabsf(f.w))));
    }
#pragma unroll
    for (int s = 16; s > 0; s >>= 1)
        m = fmaxf(m, __shfl_xor_sync(0xFFFFFFFFu, m, s));
    if (lane == 0) g_ws[v] = fmaxf(__fdiv_rn(m, 7.0f), 1e-9f);
}

// pack weight block (nt, kt): 256 rows x 64 K -> fragment-ordered 32 KB (paired)
__global__ void w_pack_kernel(const float* __restrict__ W) {
    const int nt = blockIdx.x, kt = blockIdx.y;
    const int t = threadIdx.x;
    __shared__ __align__(16) unsigned char stg[32768];
    const int v = nt * 256 + t, na = t >> 3, nn = t & 7;
    const float* wrow = W + (size_t)v * HID + kt * 64;
    const float s = g_ws[v];
#pragma unroll
    for (int i = 0; i < 32; i++) {
        const int k0 = 2 * i;
        const int ka = k0 >> 4, kk = k0 & 15;
        const int kp = ka >> 1;
        const int lane = nn * 4 + ((kk & 7) >> 1);
        const float e0 = qclamp(wrow[k0],     s);
        const float e1 = qclamp(wrow[k0 + 1], s);
        const uint32_t off = (uint32_t)(((kp * 32 + na) * 32 + lane) * 16 +
                                        (ka & 1) * 8 + (kk >> 3) * 4);
        *reinterpret_cast<uint32_t*>(stg + off) = bf16x2(e0, e1);
    }
    __syncthreads();
    uint4* dst = reinterpret_cast<uint4*>(g_wb + ((size_t)(kt * NTL + nt) << 15));
    const uint4* src = reinterpret_cast<const uint4*>(stg);
#pragma unroll
    for (int i = 0; i < 8; i++) dst[t + i * 256] = src[t + i * 256];
}

// per-(chunk, channel) abs max over 256 rows + per-chunk max
__global__ void chunk_cmax_kernel(const float* __restrict__ X) {
    const int c  = blockIdx.x;
    const int ch = blockIdx.y * 256 + threadIdx.x;
    const float* p = X + (size_t)c * 256 * HID + ch;
    float m = 0.0f;
#pragma unroll 8
    for (int r = 0; r < 256; r++) m = fmaxf(m, fabsf(p[(size_t)r * HID]));
    g_cmax[c * HID + ch] = m;
    __shared__ float red[256];
    red[threadIdx.x] = m;
    __syncthreads();
    for (int s = 128; s > 0; s >>= 1) {
        if (threadIdx.x < s)
            red[threadIdx.x] = fmaxf(red[threadIdx.x], red[threadIdx.x + s]);
        __syncthreads();
    }
    if (threadIdx.x == 0)
        atomicMax(&g_tmax_i[c], __float_as_int(red[0]));  // nonneg floats
}

__global__ void chunk_scales_kernel() {
    const int idx = blockIdx.x * 256 + threadIdx.x;   // NCHUNK*HID = 65536
    const int c = idx >> 12;
    const float tmax = __int_as_float(g_tmax_i[c]);
    const float cm = g_cmax[idx];
    int b = 0;
#pragma unroll
    for (int i = 0; i < 13; i++) b += (cm > ldexpf(tmax, i - 13)) ? 1 : 0;
    g_sx[idx]   = fmaxf(__fdiv_rn(ldexpf(tmax, b - 13), 7.0f), 1e-9f);
    g_mult[idx] = ldexpf(1.0f, b - 8);   // exact pow2 emit multiplier
}

// pack activation block (mt, kt): 128 rows x 64 K -> fragment-ordered 16 KB
__global__ void x_pack_kernel(const float* __restrict__ X) {
    const int mt = blockIdx.x, kt = blockIdx.y;
    const int t = threadIdx.x;
    __shared__ __align__(16) unsigned char stg[16384];
    const int r = t >> 1, hh = (t & 1) * 32;
    const int token = mt * 128 + r;
    const int chunk = token >> 8;
    const float* xrow = X + (size_t)token * HID + kt * 64 + hh;
    const float* sx = g_sx   + chunk * HID + kt * 64 + hh;
    const float* ml = g_mult + chunk * HID + kt * 64 + hh;
    const int mm = r & 15, ma = r >> 4;
#pragma unroll
    for (int i = 0; i < 16; i++) {
        const int h0 = 2 * i;
        const int kl = hh + h0;
        const int ka = kl >> 4, kk = kl & 15;
        const float e0 = qclamp(xrow[h0],     sx[h0])     * ml[h0];
        const float e1 = qclamp(xrow[h0 + 1], sx[h0 + 1]) * ml[h0 + 1];
        const uint32_t off = (uint32_t)((ka * 8 + ma) * 512 +
                              ((mm & 7) * 4 + ((kk & 7) >> 1)) * 16 +
                              ((kk >> 3) * 2 + (mm >> 3)) * 4);
        *reinterpret_cast<uint32_t*>(stg + off) = bf16x2(e0, e1);
    }
    __syncthreads();
    uint4* dst = reinterpret_cast<uint4*>(g_xa + ((size_t)(kt * MT + mt) << 14));
    const uint4* src = reinterpret_cast<const uint4*>(stg);
#pragma unroll
    for (int i = 0; i < 4; i++) dst[t + i * 256] = src[t + i * 256];
}

// --------------------------------- GEMM ------------------------------------
// 128(M) x 256(N) CTA tile, 8 warps (2m x 4n) of 64x64, K stage 64, 4 stages.
#define STAGES 4
#define STG_BYTES 49152   // A 16 KB + B 32 KB

__global__ void __launch_bounds__(256, 1) gemm_kernel(float* __restrict__ out) {
    extern __shared__ __align__(16) unsigned char dyn[];
    __shared__ float s_sw[256];
    const int tid = threadIdx.x;
    const int wid = tid >> 5, lid = tid & 31;
    const int mt = blockIdx.x, nt = blockIdx.y;
    const int wm = wid >> 2, wn = wid & 3;
    const uint32_t sbase = smem_u32(dyn);

    s_sw[tid] = g_ws[nt * 256 + tid];

    auto fetch = [&](int s, int kt) {
        const uint32_t d = sbase + s * STG_BYTES + tid * 16;
        const unsigned char* a = g_xa + (((size_t)kt * MT + mt) << 14) + tid * 16;
        const unsigned char* b = g_wb + (((size_t)kt * NTL + nt) << 15) + tid * 16;
#pragma unroll
        for (int i = 0; i < 4; i++) CP_ASYNC16(d + i * 4096, a + i * 4096);
#pragma unroll
        for (int i = 0; i < 8; i++)
            CP_ASYNC16(d + 16384 + i * 4096, b + i * 4096);
    };

    float acc[4][8][4];
#pragma unroll
    for (int i = 0; i < 4; i++)
#pragma unroll
        for (int j = 0; j < 8; j++)
#pragma unroll
            for (int k = 0; k < 4; k++) acc[i][j][k] = 0.0f;

    fetch(0, 0); CP_COMMIT();
    fetch(1, 1); CP_COMMIT();
    fetch(2, 2); CP_COMMIT();

#pragma unroll 1
    for (int kt = 0; kt < KT64; kt++) {
        CP_WAIT2();
        __syncthreads();
        if (kt + 3 < KT64) fetch((kt + 3) & 3, kt + 3);
        CP_COMMIT();
        const unsigned char* st = dyn + (kt & 3) * STG_BYTES;
#pragma unroll
        for (int kp = 0; kp < 2; kp++) {
            // B: one LDS.128 per na covers both ka of this pair
            uint4 bq[8];
#pragma unroll
            for (int na = 0; na < 8; na++)
                bq[na] = *reinterpret_cast<const uint4*>(
                    st + 16384 + ((kp * 32 + wn * 8 + na) * 32 + lid) * 16);
            uint32_t af[2][4][4];
#pragma unroll
            for (int kb = 0; kb < 2; kb++)
#pragma unroll
                for (int ma = 0; ma < 4; ma++) {
                    const uint4 q = *reinterpret_cast<const uint4*>(
                        st + ((kp * 2 + kb) * 8 + wm * 4 + ma) * 512 + lid * 16);
                    af[kb][ma][0] = q.x; af[kb][ma][1] = q.y;
                    af[kb][ma][2] = q.z; af[kb][ma][3] = q.w;
                }
#pragma unroll
            for (int ma = 0; ma < 4; ma++)
#pragma unroll
                for (int na = 0; na < 8; na++) {
                    const uint32_t b0[2] = { bq[na].x, bq[na].y };
                    const uint32_t b1[2] = { bq[na].z, bq[na].w };
                    mma16816(acc[ma][na], af[0][ma], b0);
                    mma16816(acc[ma][na], af[1][ma], b1);
                }
        }
    }

    // epilogue: acc * alpha[chunk] * sw[v]
    const float alpha =
        __fdiv_rn(__int_as_float(g_tmax_i[mt >> 1]), 7.0f) * 0.03125f;
    const int row_base = mt * 128 + wm * 64;
    const int col_cta = nt * 256;
#pragma unroll
    for (int ma = 0; ma < 4; ma++) {
#pragma unroll
        for (int na = 0; na < 8; na++) {
            const int r0 = row_base + ma * 16 + (lid >> 2);
            const int c0 = wn * 64 + na * 8 + (lid & 3) * 2;
            const float f0 = s_sw[c0] * alpha, f1 = s_sw[c0 + 1] * alpha;
            float* p = out + (size_t)r0 * VOCAB + col_cta + c0;
            float2 v0, v1;
            v0.x = acc[ma][na][0] * f0; v0.y = acc[ma][na][1] * f1;
            v1.x = acc[ma][na][2] * f0; v1.y = acc[ma][na][3] * f1;
            *reinterpret_cast<float2*>(p) = v0;
            *reinterpret_cast<float2*>(p + (size_t)8 * VOCAB) = v1;
        }
    }
}

// ------------------------------- launcher ----------------------------------
extern "C" void kernel_launch(void* const* d_in, const int* in_sizes, int n_in,
                              void* d_out, int out_size) {
    const float* hs = (const float*)d_in[0];   // [2,2048,4096]
    const float* W  = (const float*)d_in[1];   // [32000,4096]
    float* out = (float*)d_out;

    cudaFuncSetAttribute(gemm_kernel,
                         cudaFuncAttributeMaxDynamicSharedMemorySize,
                         STAGES * STG_BYTES);

    // 6 launches total -> gemm is launch #6, so ncu (-s 5 -c 1) profiles it
    w_scale_kernel<<<VOCAB / 8, 256>>>(W);
    w_pack_kernel<<<dim3(NTL, KT64), 256>>>(W);
    chunk_cmax_kernel<<<dim3(NCHUNK, HID / 256), 256>>>(hs);
    chunk_scales_kernel<<<NCHUNK * HID / 256, 256>>>();
    x_pack_kernel<<<dim3(MT, KT64), 256>>>(hs);
    gemm_kernel<<<dim3(MT, NTL), 256, STAGES * STG_BYTES>>>(out);
}

// round 6
// speedup vs baseline: 1.8250x; 1.4193x over previous
#include <cuda_runtime.h>
#include <cstdint>

#define TOKENS 4096
#define HID    4096
#define VOCAB  32000
#define NCHUNK 16
#define MT     32      // 4096/128 m tiles
#define NTL    125     // 32000/256 n tiles
#define KT64   64      // 4096/64 k stage-chunks

// ---------------- device scratch (static; no cudaMalloc) -------------------
// bf16 fragment-ordered operands for mma.sync m16n8k16 (R3 layout):
// g_xa: A block (kt,mt) = 16384 B at ((kt*MT+mt)<<14)
//   off = (ka*8+ma)*512 + ((mm&7)*4 + ((kk&7)>>1))*16 + ((kk>>3)*2 + (mm>>3))*4
// g_wb: B block (kt,nt) = 32768 B at ((kt*NTL+nt)<<15)
//   off = (ka*32+na)*256 + nn*32 + ((kk&7)>>1)*8 + (kk>>3)*4
__device__ __align__(16) unsigned char g_xa[(size_t)TOKENS * HID * 2];
__device__ __align__(16) unsigned char g_wb[(size_t)VOCAB * HID * 2];
__device__ float g_ws[VOCAB];
__device__ float g_cmax[NCHUNK * HID];
__device__ float g_part[NCHUNK * 16];
__device__ float g_tmaxf[NCHUNK];
__device__ float g_sx[NCHUNK * HID];
__device__ float g_mult[NCHUNK * HID];

// ------------------------------ helpers ------------------------------------
__device__ __forceinline__ uint32_t smem_u32(const void* p) {
    uint32_t a;
    asm("{ .reg .u64 t; cvta.to.shared.u64 t, %1; cvt.u32.u64 %0, t; }"
        : "=r"(a) : "l"(p));
    return a;
}
__device__ __forceinline__ float qclamp(float x, float s) {
    // matches jnp.clip(jnp.round(x/s), -8, 7), round-half-to-even, rn divide
    return fminf(fmaxf(rintf(__fdiv_rn(x, s)), -8.0f), 7.0f);
}
__device__ __forceinline__ uint32_t bf16x2(float lo, float hi) {
    uint32_t r;
    asm("cvt.rn.bf16x2.f32 %0, %1, %2;" : "=r"(r) : "f"(hi), "f"(lo));
    return r;
}
__device__ __forceinline__ void mma16816(float* c, const uint32_t* a,
                                         const uint32_t* b) {
    asm volatile(
        "mma.sync.aligned.m16n8k16.row.col.f32.bf16.bf16.f32 "
        "{%0,%1,%2,%3}, {%4,%5,%6,%7}, {%8,%9}, {%0,%1,%2,%3};"
        : "+f"(c[0]), "+f"(c[1]), "+f"(c[2]), "+f"(c[3])
        : "r"(a[0]), "r"(a[1]), "r"(a[2]), "r"(a[3]), "r"(b[0]), "r"(b[1]));
}
#define CP_ASYNC16(dst_u32, src_ptr) \
    asm volatile("cp.async.cg.shared.global [%0], [%1], 16;" \
                 :: "r"(dst_u32), "l"(src_ptr) : "memory")
#define CP_COMMIT()  asm volatile("cp.async.commit_group;" ::: "memory")
#define CP_WAIT2()   asm volatile("cp.async.wait_group 2;" ::: "memory")

// ------------------------------ prep launch 1 -------------------------------
// blocks [0,4000): weight scale+pack, warp per vocab row (8 rows/block)
// blocks [4000,4256): activation per-(chunk,channel) abs-max partials
__global__ void prep1_kernel(const float* __restrict__ W,
                             const float* __restrict__ X) {
    if (blockIdx.x < 4000) {
        const int w = threadIdx.x >> 5, lane = threadIdx.x & 31;
        const int v = blockIdx.x * 8 + w;
        const float* row = W + (size_t)v * HID;
        const float4* r4 = reinterpret_cast<const float4*>(row);
        float m = 0.0f;
#pragma unroll
        for (int j = 0; j < 32; j++) {
            float4 f = r4[lane + j * 32];
            m = fmaxf(m, fmaxf(fmaxf(fabsf(f.x), fabsf(f.y)),
                               fmaxf(fabsf(f.z), fabsf(f.w))));
        }
#pragma unroll
        for (int s = 16; s > 0; s >>= 1)
            m = fmaxf(m, __shfl_xor_sync(0xFFFFFFFFu, m, s));
        const float sc = fmaxf(__fdiv_rn(__shfl_sync(0xFFFFFFFFu, m, 0), 7.0f),
                               1e-9f);
        if (lane == 0) g_ws[v] = sc;
        // pack: lane handles chunk c = i*32+lane (kt=c>>2, ka=c&3), 16 k each
        const int nt = v >> 8, na = (v & 255) >> 3, nn = v & 7;
        unsigned char* base = g_wb + ((size_t)nt << 15) + na * 256 + nn * 32;
#pragma unroll 1
        for (int i = 0; i < 8; i++) {
            const int c = i * 32 + lane;
            const int kt = c >> 2, ka = c & 3;
            const float4 f0 = r4[c * 4 + 0], f1 = r4[c * 4 + 1];
            const float4 f2 = r4[c * 4 + 2], f3 = r4[c * 4 + 3];
            // word w: kk = (w&1)*8 + (w>>1)*2 -> pairs (kk, kk+1)
            uint4 o0, o1;
            o0.x = bf16x2(qclamp(f0.x, sc), qclamp(f0.y, sc));   // kk=0,1
            o0.y = bf16x2(qclamp(f2.x, sc), qclamp(f2.y, sc));   // kk=8,9
            o0.z = bf16x2(qclamp(f0.z, sc), qclamp(f0.w, sc));   // kk=2,3
            o0.w = bf16x2(qclamp(f2.z, sc), qclamp(f2.w, sc));   // kk=10,11
            o1.x = bf16x2(qclamp(f1.x, sc), qclamp(f1.y, sc));   // kk=4,5
            o1.y = bf16x2(qclamp(f3.x, sc), qclamp(f3.y, sc));   // kk=12,13
            o1.z = bf16x2(qclamp(f1.z, sc), qclamp(f1.w, sc));   // kk=6,7
            o1.w = bf16x2(qclamp(f3.z, sc), qclamp(f3.w, sc));   // kk=14,15
            unsigned char* dst = base + (size_t)kt * NTL * 32768 + ka * 8192;
            *reinterpret_cast<uint4*>(dst)      = o0;
            *reinterpret_cast<uint4*>(dst + 16) = o1;
        }
    } else {
        const int b = blockIdx.x - 4000;
        const int c = b >> 4, cb = b & 15;
        const int ch = cb * 256 + threadIdx.x;
        const float* p = X + (size_t)c * 256 * HID + ch;
        float m = 0.0f;
#pragma unroll 8
        for (int r = 0; r < 256; r++) m = fmaxf(m, fabsf(p[(size_t)r * HID]));
        g_cmax[c * HID + ch] = m;
        __shared__ float red[256];
        red[threadIdx.x] = m;
        __syncthreads();
        for (int s = 128; s > 0; s >>= 1) {
            if (threadIdx.x < s)
                red[threadIdx.x] = fmaxf(red[threadIdx.x], red[threadIdx.x + s]);
            __syncthreads();
        }
        if (threadIdx.x == 0) g_part[c * 16 + cb] = red[0];
    }
}

// ------------------------------ prep launch 2 -------------------------------
__global__ void chunk_scales_kernel() {
    const int idx = blockIdx.x * 256 + threadIdx.x;   // NCHUNK*HID = 65536
    const int c = idx >> 12;
    float tmax = 0.0f;
#pragma unroll
    for (int j = 0; j < 16; j++) tmax = fmaxf(tmax, g_part[c * 16 + j]);
    if ((idx & 4095) == 0) g_tmaxf[c] = tmax;
    const float cm = g_cmax[idx];
    int b = 0;
#pragma unroll
    for (int i = 0; i < 13; i++) b += (cm > ldexpf(tmax, i - 13)) ? 1 : 0;
    g_sx[idx]   = fmaxf(__fdiv_rn(ldexpf(tmax, b - 13), 7.0f), 1e-9f);
    g_mult[idx] = ldexpf(1.0f, b - 8);   // exact pow2 emit multiplier
}

// ------------------------------ prep launch 3 -------------------------------
// pack activation block (mt, kt): 128 rows x 64 K -> fragment-ordered 16 KB
__global__ void x_pack_kernel(const float* __restrict__ X) {
    const int mt = blockIdx.x, kt = blockIdx.y;
    const int t = threadIdx.x;
    __shared__ __align__(16) unsigned char stg[16384];
    const int r = t >> 1, hh = (t & 1) * 32;
    const int token = mt * 128 + r;
    const int chunk = token >> 8;
    const float* xrow = X + (size_t)token * HID + kt * 64 + hh;
    const float* sx = g_sx   + chunk * HID + kt * 64 + hh;
    const float* ml = g_mult + chunk * HID + kt * 64 + hh;
    const int mm = r & 15, ma = r >> 4;
#pragma unroll
    for (int i = 0; i < 16; i++) {
        const int h0 = 2 * i;
        const int kl = hh + h0;
        const int ka = kl >> 4, kk = kl & 15;
        const float e0 = qclamp(xrow[h0],     sx[h0])     * ml[h0];
        const float e1 = qclamp(xrow[h0 + 1], sx[h0 + 1]) * ml[h0 + 1];
        const uint32_t off = (uint32_t)((ka * 8 + ma) * 512 +
                              ((mm & 7) * 4 + ((kk & 7) >> 1)) * 16 +
                              ((kk >> 3) * 2 + (mm >> 3)) * 4);
        *reinterpret_cast<uint32_t*>(stg + off) = bf16x2(e0, e1);
    }
    __syncthreads();
    uint4* dst = reinterpret_cast<uint4*>(g_xa + ((size_t)(kt * MT + mt) << 14));
    const uint4* src = reinterpret_cast<const uint4*>(stg);
#pragma unroll
    for (int i = 0; i < 4; i++) dst[t + i * 256] = src[t + i * 256];
}

// --------------------------------- GEMM (launch 4) --------------------------
// 128(M) x 256(N) CTA tile, 8 warps (2m x 4n) of 64x64, K stage 64, 4 stages.
#define STAGES 4
#define STG_BYTES 49152   // A 16 KB + B 32 KB

__global__ void __launch_bounds__(256, 1) gemm_kernel(float* __restrict__ out) {
    extern __shared__ __align__(16) unsigned char dyn[];
    __shared__ float s_sw[256];
    const int tid = threadIdx.x;
    const int wid = tid >> 5, lid = tid & 31;
    const int mt = blockIdx.x, nt = blockIdx.y;
    const int wm = wid >> 2, wn = wid & 3;
    const uint32_t sbase = smem_u32(dyn);

    s_sw[tid] = g_ws[nt * 256 + tid];

    auto fetch = [&](int s, int kt) {
        const uint32_t d = sbase + s * STG_BYTES + tid * 16;
        const unsigned char* a = g_xa + (((size_t)kt * MT + mt) << 14) + tid * 16;
        const unsigned char* b = g_wb + (((size_t)kt * NTL + nt) << 15) + tid * 16;
#pragma unroll
        for (int i = 0; i < 4; i++) CP_ASYNC16(d + i * 4096, a + i * 4096);
#pragma unroll
        for (int i = 0; i < 8; i++)
            CP_ASYNC16(d + 16384 + i * 4096, b + i * 4096);
    };

    float acc[4][8][4];
#pragma unroll
    for (int i = 0; i < 4; i++)
#pragma unroll
        for (int j = 0; j < 8; j++)
#pragma unroll
            for (int k = 0; k < 4; k++) acc[i][j][k] = 0.0f;

    fetch(0, 0); CP_COMMIT();
    fetch(1, 1); CP_COMMIT();
    fetch(2, 2); CP_COMMIT();

#pragma unroll 1
    for (int kt = 0; kt < KT64; kt++) {
        CP_WAIT2();
        __syncthreads();
        const unsigned char* st = dyn + (kt & 3) * STG_BYTES;
#pragma unroll
        for (int ka = 0; ka < 4; ka++) {
            uint32_t af[4][4], bf[8][2];
#pragma unroll
            for (int ma = 0; ma < 4; ma++) {
                const uint4 q = *reinterpret_cast<const uint4*>(
                    st + (ka * 8 + wm * 4 + ma) * 512 + lid * 16);
                af[ma][0] = q.x; af[ma][1] = q.y; af[ma][2] = q.z; af[ma][3] = q.w;
            }
#pragma unroll
            for (int na = 0; na < 8; na++) {
                const uint2 q = *reinterpret_cast<const uint2*>(
                    st + 16384 + (ka * 32 + wn * 8 + na) * 256 + lid * 8);
                bf[na][0] = q.x; bf[na][1] = q.y;
            }
#pragma unroll
            for (int ma = 0; ma < 4; ma++)
#pragma unroll
                for (int na = 0; na < 8; na++)
                    mma16816(acc[ma][na], af[ma], bf[na]);
        }
        if (kt + 3 < KT64) fetch((kt + 3) & 3, kt + 3);
        CP_COMMIT();
    }

    // epilogue: acc * alpha[chunk] * sw[v]
    const float alpha = __fdiv_rn(g_tmaxf[mt >> 1], 7.0f) * 0.03125f;
    const int row_base = mt * 128 + wm * 64;
    const int col_cta = nt * 256;
#pragma unroll
    for (int ma = 0; ma < 4; ma++) {
#pragma unroll
        for (int na = 0; na < 8; na++) {
            const int r0 = row_base + ma * 16 + (lid >> 2);
            const int c0 = wn * 64 + na * 8 + (lid & 3) * 2;
            const float f0 = s_sw[c0] * alpha, f1 = s_sw[c0 + 1] * alpha;
            float* p = out + (size_t)r0 * VOCAB + col_cta + c0;
            float2 v0, v1;
            v0.x = acc[ma][na][0] * f0; v0.y = acc[ma][na][1] * f1;
            v1.x = acc[ma][na][2] * f0; v1.y = acc[ma][na][3] * f1;
            *reinterpret_cast<float2*>(p) = v0;
            *reinterpret_cast<float2*>(p + (size_t)8 * VOCAB) = v1;
        }
    }
}

// ------------------------------- launcher ----------------------------------
extern "C" void kernel_launch(void* const* d_in, const int* in_sizes, int n_in,
                              void* d_out, int out_size) {
    const float* hs = (const float*)d_in[0];   // [2,2048,4096]
    const float* W  = (const float*)d_in[1];   // [32000,4096]
    float* out = (float*)d_out;

    cudaFuncSetAttribute(gemm_kernel,
                         cudaFuncAttributeMaxDynamicSharedMemorySize,
                         STAGES * STG_BYTES);

    // exactly 4 launches: harness offset (2) + 3 preps puts gemm at ncu's
    // profiled slot (-s 5 -c 1) next round.
    prep1_kernel<<<4256, 256>>>(W, hs);
    chunk_scales_kernel<<<NCHUNK * HID / 256, 256>>>();
    x_pack_kernel<<<dim3(MT, KT64), 256>>>(hs);
    gemm_kernel<<<dim3(MT, NTL), 256, STAGES * STG_BYTES>>>(out);
}